// round 7
// baseline (speedup 1.0000x reference)
#include <cuda_runtime.h>

// Problem constants
#define INSZ   128
#define OUTSZ  128
#define BATCH  1024

#define NCHUNK 8
#define BC     (BATCH / NCHUNK)   // 128 batch elems per block
#define PAD    133                // smem row pitch (conflict-free staging writes)

typedef unsigned long long u64;

__device__ __forceinline__ u64 pk(float a, float b) {
    u64 r; asm("mov.b64 %0, {%1, %2};" : "=l"(r) : "f"(a), "f"(b)); return r;
}
__device__ __forceinline__ void upk(u64 v, float& a, float& b) {
    asm("mov.b64 {%0, %1}, %2;" : "=f"(a), "=f"(b) : "l"(v));
}
__device__ __forceinline__ u64 ffma2(u64 a, u64 b, u64 c) {
    u64 d; asm("fma.rn.f32x2 %0, %1, %2, %3;" : "=l"(d) : "l"(a), "l"(b), "l"(c)); return d;
}
__device__ __forceinline__ u64 fmul2(u64 a, u64 b) {
    u64 d; asm("mul.rn.f32x2 %0, %1, %2;" : "=l"(d) : "l"(a), "l"(b)); return d;
}
__device__ __forceinline__ u64 fadd2(u64 a, u64 b) {
    u64 d; asm("add.rn.f32x2 %0, %1, %2;" : "=l"(d) : "l"(a), "l"(b)); return d;
}

// ---------------------------------------------------------------------------
// Fused kernel: block = (o, batch-chunk of 128); thread = input feature i.
// K-PACKED layer 2: f32x2 lanes carry (k, k+1) of the reduction dim, so the
// relu'd layer-1 output pairs feed layer-2 chains directly — no splat MOVs.
// Per elem: ~51 fma-pipe ops, ~20 alu-pipe ops (was ~45 + ~40).
// ---------------------------------------------------------------------------
__global__ void __launch_bounds__(128, 3)
mlpkan_fused(const float* __restrict__ x,
             const float* __restrict__ W1, const float* __restrict__ b1,
             const float* __restrict__ W2, const float* __restrict__ b2,
             const float* __restrict__ W3, const float* __restrict__ b3,
             float* __restrict__ out) {
    const int o     = blockIdx.x;
    const int chunk = blockIdx.y;
    const int i     = threadIdx.x;

    __shared__ float sm[49 * PAD];          // 26.1 KB: staging, then red/pr alias
    float* red = sm;                        // [32][129] padded
    float* pr  = sm + 32 * 129;             // [4][33]

    // ---- start x prefetch first so memory latency overlaps weight staging ----
    const float* xp = x + (size_t)chunk * BC * INSZ + i;
    float vbuf[8];
#pragma unroll
    for (int p = 0; p < 8; p++) vbuf[p] = xp[(size_t)p * INSZ];

    // =========== Phase A staging: W1 (f0-7), b1 (f8-15), W2 e<32 (f16-47) ====
#pragma unroll
    for (int r = 0; r < 8; r++) {
        int idx = r * 128 + i, ii = idx >> 3, h = idx & 7;
        sm[h * PAD + ii] = W1[(size_t)(ii * OUTSZ + o) * 8 + h];
    }
#pragma unroll
    for (int r = 0; r < 8; r++) {
        int idx = r * 128 + i, ii = idx >> 3, h = idx & 7;
        sm[(8 + h) * PAD + ii] = b1[(size_t)(ii * OUTSZ + o) * 8 + h];
    }
#pragma unroll
    for (int r = 0; r < 32; r++) {
        int idx = r * 128 + i, ii = idx >> 5, e = idx & 31;
        sm[(16 + e) * PAD + ii] = W2[(size_t)(ii * OUTSZ + o) * 64 + e];
    }
    __syncthreads();

    // layer-1 stays hidden-packed: w1p[p] = (w1[2p], w1[2p+1])
    u64 w1p[4], b1p[4];
    // layer-2 K-PACKED: w2p[j][kp] = (W2[j][2kp], W2[j][2kp+1])
    u64 w2p[8][4];
#pragma unroll
    for (int p = 0; p < 4; p++) {
        w1p[p] = pk(sm[(2 * p) * PAD + i], sm[(2 * p + 1) * PAD + i]);
        b1p[p] = pk(sm[(8 + 2 * p) * PAD + i], sm[(9 + 2 * p) * PAD + i]);
    }
#pragma unroll
    for (int j = 0; j < 4; j++)            // e = j*8 + k, e<32 -> j=0..3
#pragma unroll
        for (int kp = 0; kp < 4; kp++)
            w2p[j][kp] = pk(sm[(16 + j * 8 + 2 * kp) * PAD + i],
                            sm[(16 + j * 8 + 2 * kp + 1) * PAD + i]);
    __syncthreads();

    // ===== Phase B staging: W2 e>=32 (r0-31), b2 (r32-39), W3 (r40-47), b3 (r48)
#pragma unroll
    for (int r = 0; r < 32; r++) {
        int idx = r * 128 + i, ii = idx >> 5, e = idx & 31;
        sm[e * PAD + ii] = W2[(size_t)(ii * OUTSZ + o) * 64 + 32 + e];
    }
#pragma unroll
    for (int r = 0; r < 8; r++) {
        int idx = r * 128 + i, ii = idx >> 3, h = idx & 7;
        sm[(32 + h) * PAD + ii] = b2[(size_t)(ii * OUTSZ + o) * 8 + h];
    }
#pragma unroll
    for (int r = 0; r < 8; r++) {
        int idx = r * 128 + i, ii = idx >> 3, h = idx & 7;
        sm[(40 + h) * PAD + ii] = W3[(size_t)(ii * OUTSZ + o) * 8 + h];
    }
    sm[48 * PAD + i] = b3[(size_t)i * OUTSZ + o];
    __syncthreads();

    u64 b2p[8], w3p[4], b3p;
#pragma unroll
    for (int j = 0; j < 4; j++)            // j = 4..7
#pragma unroll
        for (int kp = 0; kp < 4; kp++)
            w2p[4 + j][kp] = pk(sm[(j * 8 + 2 * kp) * PAD + i],
                                sm[(j * 8 + 2 * kp + 1) * PAD + i]);
#pragma unroll
    for (int j = 0; j < 8; j++)
        b2p[j] = pk(sm[(32 + j) * PAD + i], 0.0f);   // bias in low lane
#pragma unroll
    for (int p = 0; p < 4; p++)
        w3p[p] = pk(sm[(40 + 2 * p) * PAD + i], sm[(41 + 2 * p) * PAD + i]);
    b3p = pk(sm[48 * PAD + i], 0.0f);
    __syncthreads();                        // sm now reusable as red/pr

#pragma unroll 1
    for (int sub = 0; sub < BC / 32; sub++) {
#pragma unroll 1
        for (int g = 0; g < 4; g++) {
#pragma unroll
            for (int u = 0; u < 8; u++) {
                const int b = sub * 32 + g * 8 + u;   // batch elem within chunk
                float v = vbuf[u];
                const int pb = b + 8;                  // prefetch 8 ahead
                if (pb < BC) vbuf[u] = xp[(size_t)pb * INSZ];

                u64 vp = pk(v, v);

                // layer 1: s[p] = relu(w1*v + b1), kept as (2p, 2p+1) pairs.
                // Repack after FMNMX is register-allocation only (no splat).
                u64 s[4];
#pragma unroll
                for (int p = 0; p < 4; p++) {
                    u64 t = ffma2(w1p[p], vp, b1p[p]);
                    float ta, tb; upk(t, ta, tb);
                    s[p] = pk(fmaxf(ta, 0.0f), fmaxf(tb, 0.0f));
                }

                // layer 2: k-packed. 8 independent 4-deep chains; horizontal
                // add folds the packed (bias, 0) init. One scalar relu per j.
                float h[8];
#pragma unroll
                for (int j = 0; j < 8; j++) {
                    u64 acc = ffma2(w2p[j][0], s[0], b2p[j]);
                    acc = ffma2(w2p[j][1], s[1], acc);
                    acc = ffma2(w2p[j][2], s[2], acc);
                    acc = ffma2(w2p[j][3], s[3], acc);
                    float lo, hi; upk(acc, lo, hi);
                    h[j] = fmaxf(lo + hi, 0.0f);
                }

                // layer 3: pack h pairs (reg-alloc), two 2-deep chains
                u64 hp0 = pk(h[0], h[1]), hp1 = pk(h[2], h[3]);
                u64 hp2 = pk(h[4], h[5]), hp3 = pk(h[6], h[7]);
                u64 a0 = ffma2(w3p[0], hp0, b3p);
                u64 a1 = fmul2(w3p[1], hp1);
                a0 = ffma2(w3p[2], hp2, a0);
                a1 = ffma2(w3p[3], hp3, a1);
                u64 t = fadd2(a0, a1);
                float x0, x1; upk(t, x0, x1);

                red[(g * 8 + u) * 129 + i] = x0 + x1;
            }
        }
        __syncthreads();

        // spread reduction: thread t sums i-slice [32*(t>>5), +32) of bb = t&31
        {
            const int rb = i & 31, rq = i >> 5;
            const float* rr = &red[rb * 129 + rq * 32];
            float s0 = 0.f, s1 = 0.f, s2 = 0.f, s3 = 0.f;
#pragma unroll
            for (int c = 0; c < 32; c += 4) {
                s0 += rr[c + 0]; s1 += rr[c + 1];
                s2 += rr[c + 2]; s3 += rr[c + 3];
            }
            pr[rq * 33 + rb] = (s0 + s1) + (s2 + s3);
        }
        __syncthreads();

        // 4-way combine + store (one warp; overlapped with next sub's compute)
        if (i < 32) {
            float r = (pr[i] + pr[33 + i]) + (pr[66 + i] + pr[99 + i]);
            out[(size_t)(chunk * BC + sub * 32 + i) * OUTSZ + o] = r;
        }
    }
}

// ---------------------------------------------------------------------------
extern "C" void kernel_launch(void* const* d_in, const int* in_sizes, int n_in,
                              void* d_out, int out_size) {
    const float* x  = (const float*)d_in[0];
    const float* W1 = (const float*)d_in[1];
    const float* b1 = (const float*)d_in[2];
    const float* W2 = (const float*)d_in[3];
    const float* b2 = (const float*)d_in[4];
    const float* W3 = (const float*)d_in[5];
    const float* b3 = (const float*)d_in[6];
    float* out = (float*)d_out;

    mlpkan_fused<<<dim3(OUTSZ, NCHUNK), INSZ>>>(x, W1, b1, W2, b2, W3, b3, out);
}

// round 8
// speedup vs baseline: 1.0166x; 1.0166x over previous
#include <cuda_runtime.h>
#include <cstdint>

// Problem constants
#define INSZ   128
#define OUTSZ  128
#define BATCH  1024

#define NCHUNK 8
#define BC     (BATCH / NCHUNK)   // 128 batch elems per block

typedef unsigned long long u64;

__device__ __forceinline__ u64 pk(float a, float b) {
    u64 r; asm("mov.b64 %0, {%1, %2};" : "=l"(r) : "f"(a), "f"(b)); return r;
}
__device__ __forceinline__ void upk(u64 v, float& a, float& b) {
    asm("mov.b64 {%0, %1}, %2;" : "=f"(a), "=f"(b) : "l"(v));
}
__device__ __forceinline__ u64 ffma2(u64 a, u64 b, u64 c) {
    u64 d; asm("fma.rn.f32x2 %0, %1, %2, %3;" : "=l"(d) : "l"(a), "l"(b), "l"(c)); return d;
}

// Zero-init for out (atomicAdd accumulation target). 131072 floats.
__global__ void zero_out_kernel(float* __restrict__ out) {
    out[blockIdx.x * 256 + threadIdx.x] = 0.0f;
}

// ---------------------------------------------------------------------------
// Pair-split kernel. Block = (o, chunk, ihalf). 128 threads = 64 i-pairs.
// Thread (p = t>>1, c = t&1) handles i = ihalf*64+p, owning hiddens/j's
// [4c, 4c+4). Weights per thread: 50 regs -> 5 CTAs/SM (5 warps/SMSP).
// Partner exchange of relu'd splat pairs via 8 shfl; k-order permutation is
// folded into the weight staging so the hot loop is parity-free.
// ---------------------------------------------------------------------------
__global__ void __launch_bounds__(128, 5)
mlpkan_half(const float* __restrict__ x,
            const float* __restrict__ W1, const float* __restrict__ b1,
            const float* __restrict__ W2, const float* __restrict__ b2,
            const float* __restrict__ W3, const float* __restrict__ b3,
            float* __restrict__ out) {
    const int o     = blockIdx.x;
    const int chunk = blockIdx.y;
    const int ih    = blockIdx.z;
    const int t     = threadIdx.x;
    const int p     = t >> 1;       // pair index = local i
    const int c     = t & 1;        // parity: owns hiddens/j [4c, 4c+4)
    const int i     = ih * 64 + p;
    const int n     = i * OUTSZ + o;   // subnet id

    __shared__ float red[32 * 65];  // [b_sub][pair] (even lanes write)
    __shared__ float pr[4 * 33];

    // ---- x prefetch (pair lanes share the address -> broadcast) ----
    const float* xp = x + (size_t)chunk * BC * INSZ + i;
    float vbuf[8];
#pragma unroll
    for (int q = 0; q < 8; q++) vbuf[q] = xp[(size_t)q * INSZ];

    // ---- stage this thread's half-subnet weights (direct float4 loads) ----
    const float4 w1v = *(const float4*)(W1 + (size_t)n * 8 + 4 * c);
    const float4 b1v = *(const float4*)(b1 + (size_t)n * 8 + 4 * c);
    const u64 w1p0 = pk(w1v.x, w1v.y), w1p1 = pk(w1v.z, w1v.w);
    const u64 b1p0 = pk(b1v.x, b1v.y), b1p1 = pk(b1v.z, b1v.w);

    // W2 rows 4c..4c+3 (my j's), all 8 k: 32 consecutive floats.
    float W2v[32];
    {
        const float4* w2b = (const float4*)(W2 + (size_t)n * 64 + 32 * c);
#pragma unroll
        for (int q4 = 0; q4 < 8; q4++) {
            float4 vv = w2b[q4];
            W2v[q4 * 4 + 0] = vv.x; W2v[q4 * 4 + 1] = vv.y;
            W2v[q4 * 4 + 2] = vv.z; W2v[q4 * 4 + 3] = vv.w;
        }
    }
    // j-packed pairs, with k permuted so chain slot m uses global hidden
    // (m + 4c) & 7  (slot 0-3 = own hiddens, 4-7 = partner's, both parities).
    u64 w2p[2][8];
#pragma unroll
    for (int q = 0; q < 2; q++)
#pragma unroll
        for (int m = 0; m < 8; m++) {
            int kk = (m + 4 * c) & 7;
            w2p[q][m] = pk(W2v[(2 * q) * 8 + kk], W2v[(2 * q + 1) * 8 + kk]);
        }

    const float4 b2v = *(const float4*)(b2 + (size_t)n * 8 + 4 * c);
    const u64 b2p0 = pk(b2v.x, b2v.y), b2p1 = pk(b2v.z, b2v.w);
    const float4 w3v = *(const float4*)(W3 + (size_t)n * 8 + 4 * c);
    const u64 w3p0 = pk(w3v.x, w3v.y), w3p1 = pk(w3v.z, w3v.w);
    const u64 b3p = pk(c == 0 ? b3[n] : 0.0f, 0.0f);

    // ============================ main loop ================================
#pragma unroll 1
    for (int sub = 0; sub < BC / 32; sub++) {
#pragma unroll 1
        for (int g = 0; g < 4; g++) {
#pragma unroll
            for (int u = 0; u < 8; u++) {
                const int b = sub * 32 + g * 8 + u;
                float v = vbuf[u];
                if (b + 8 < BC) vbuf[u] = xp[(size_t)(b + 8) * INSZ];

                u64 vp = pk(v, v);

                // L1: own 4 pre-activations -> 4 relu'd splat pairs
                u64 t0 = ffma2(w1p0, vp, b1p0);
                u64 t1 = ffma2(w1p1, vp, b1p1);
                float a0, a1, a2, a3;
                upk(t0, a0, a1); upk(t1, a2, a3);
                a0 = fmaxf(a0, 0.0f); a1 = fmaxf(a1, 0.0f);
                a2 = fmaxf(a2, 0.0f); a3 = fmaxf(a3, 0.0f);
                u64 s0 = pk(a0, a0), s1 = pk(a1, a1);
                u64 s2 = pk(a2, a2), s3 = pk(a3, a3);

                // exchange partner's 4 splat pairs (slots 4-7 of the chain)
                u64 r0 = __shfl_xor_sync(0xffffffffu, s0, 1);
                u64 r1 = __shfl_xor_sync(0xffffffffu, s1, 1);
                u64 r2 = __shfl_xor_sync(0xffffffffu, s2, 1);
                u64 r3 = __shfl_xor_sync(0xffffffffu, s3, 1);

                // L2: 2 j-pair chains over all 8 hiddens (weights permuted)
                u64 acc0 = ffma2(w2p[0][0], s0, b2p0);
                u64 acc1 = ffma2(w2p[1][0], s0, b2p1);
                acc0 = ffma2(w2p[0][1], s1, acc0); acc1 = ffma2(w2p[1][1], s1, acc1);
                acc0 = ffma2(w2p[0][2], s2, acc0); acc1 = ffma2(w2p[1][2], s2, acc1);
                acc0 = ffma2(w2p[0][3], s3, acc0); acc1 = ffma2(w2p[1][3], s3, acc1);
                acc0 = ffma2(w2p[0][4], r0, acc0); acc1 = ffma2(w2p[1][4], r0, acc1);
                acc0 = ffma2(w2p[0][5], r1, acc0); acc1 = ffma2(w2p[1][5], r1, acc1);
                acc0 = ffma2(w2p[0][6], r2, acc0); acc1 = ffma2(w2p[1][6], r2, acc1);
                acc0 = ffma2(w2p[0][7], r3, acc0); acc1 = ffma2(w2p[1][7], r3, acc1);

                float h0, h1, h2, h3;
                upk(acc0, h0, h1); upk(acc1, h2, h3);
                u64 h01 = pk(fmaxf(h0, 0.0f), fmaxf(h1, 0.0f));
                u64 h23 = pk(fmaxf(h2, 0.0f), fmaxf(h3, 0.0f));

                // L3: own 4 j's; b3 folded in even lane's low half
                u64 aa = ffma2(w3p0, h01, b3p);
                aa = ffma2(w3p1, h23, aa);
                float z0, z1; upk(aa, z0, z1);
                float part = z0 + z1;

                // pair combine (IEEE add commutative -> both lanes identical)
                part += __shfl_xor_sync(0xffffffffu, part, 1);
                if (c == 0) red[(g * 8 + u) * 65 + p] = part;
            }
        }
        __syncthreads();

        // spread reduction over 64 pairs: thread (bb = t&31, qq = t>>5)
        {
            const int bb = t & 31, qq = t >> 5;
            const float* rr = &red[bb * 65 + qq * 16];
            float s0 = 0.f, s1 = 0.f, s2 = 0.f, s3 = 0.f;
#pragma unroll
            for (int cc = 0; cc < 16; cc += 4) {
                s0 += rr[cc + 0]; s1 += rr[cc + 1];
                s2 += rr[cc + 2]; s3 += rr[cc + 3];
            }
            pr[qq * 33 + bb] = (s0 + s1) + (s2 + s3);
        }
        __syncthreads();

        // combine + atomic add (exactly 2 contributions/elem: ih 0 and 1 ->
        // commutative 2-addend sum -> bit-deterministic)
        if (t < 32) {
            float r = (pr[t] + pr[33 + t]) + (pr[66 + t] + pr[99 + t]);
            atomicAdd(&out[(size_t)(chunk * BC + sub * 32 + t) * OUTSZ + o], r);
        }
    }
}

// ---------------------------------------------------------------------------
extern "C" void kernel_launch(void* const* d_in, const int* in_sizes, int n_in,
                              void* d_out, int out_size) {
    const float* x  = (const float*)d_in[0];
    const float* W1 = (const float*)d_in[1];
    const float* b1 = (const float*)d_in[2];
    const float* W2 = (const float*)d_in[3];
    const float* b2 = (const float*)d_in[4];
    const float* W3 = (const float*)d_in[5];
    const float* b3 = (const float*)d_in[6];
    float* out = (float*)d_out;

    zero_out_kernel<<<(BATCH * OUTSZ) / 256, 256>>>(out);
    mlpkan_half<<<dim3(OUTSZ, NCHUNK, 2), 128>>>(x, W1, b1, W2, b2, W3, b3, out);
}

// round 9
// speedup vs baseline: 1.1490x; 1.1302x over previous
#include <cuda_runtime.h>

// Problem constants
#define INSZ   128
#define OUTSZ  128
#define BATCH  1024

#define NCHUNK 8
#define BC     (BATCH / NCHUNK)   // 128 batch elems per block
#define PAD    133                // smem row pitch (conflict-free staging writes)

typedef unsigned long long u64;

__device__ __forceinline__ u64 pk(float a, float b) {
    u64 r; asm("mov.b64 %0, {%1, %2};" : "=l"(r) : "f"(a), "f"(b)); return r;
}
__device__ __forceinline__ void upk(u64 v, float& a, float& b) {
    asm("mov.b64 {%0, %1}, %2;" : "=f"(a), "=f"(b) : "l"(v));
}
__device__ __forceinline__ u64 ffma2(u64 a, u64 b, u64 c) {
    u64 d; asm("fma.rn.f32x2 %0, %1, %2, %3;" : "=l"(d) : "l"(a), "l"(b), "l"(c)); return d;
}
__device__ __forceinline__ u64 fmul2(u64 a, u64 b) {
    u64 d; asm("mul.rn.f32x2 %0, %1, %2;" : "=l"(d) : "l"(a), "l"(b)); return d;
}
__device__ __forceinline__ u64 fadd2(u64 a, u64 b) {
    u64 d; asm("add.rn.f32x2 %0, %1, %2;" : "=l"(d) : "l"(a), "l"(b)); return d;
}

// ---------------------------------------------------------------------------
// Fused kernel: block = (o, batch-chunk of 128); thread = input feature i.
// j-packed f32x2 core (best ledger: ~41 FFMA2 + ~30 alu per elem).
// Depth-8 wrap-around x prefetch (no predicate); reduction every 64 elems
// (2 barriers per 64, was per 32); 4 CTAs/SM.
// ---------------------------------------------------------------------------
__global__ void __launch_bounds__(128, 4)
mlpkan_fused(const float* __restrict__ x,
             const float* __restrict__ W1, const float* __restrict__ b1,
             const float* __restrict__ W2, const float* __restrict__ b2,
             const float* __restrict__ W3, const float* __restrict__ b3,
             float* __restrict__ out) {
    const int o     = blockIdx.x;
    const int chunk = blockIdx.y;
    const int i     = threadIdx.x;

    // union: staging (49*PAD = 6517 floats) vs red (64*129) + pr (4*65)
    __shared__ float sm[64 * 129 + 4 * 65];   // 34.1 KB
    float* red = sm;                          // [64][129]
    float* pr  = sm + 64 * 129;               // [4][65]

    // ---- x prefetch first: 8-deep rolling buffer ----
    const float* xp = x + (size_t)chunk * BC * INSZ + i;
    float vbuf[8];
#pragma unroll
    for (int p = 0; p < 8; p++) vbuf[p] = xp[(size_t)p * INSZ];

    // =========== Phase A staging: W1 (f0-7), b1 (f8-15), W2 e<32 (f16-47) ====
#pragma unroll
    for (int r = 0; r < 8; r++) {
        int idx = r * 128 + i, ii = idx >> 3, h = idx & 7;
        sm[h * PAD + ii] = W1[(size_t)(ii * OUTSZ + o) * 8 + h];
    }
#pragma unroll
    for (int r = 0; r < 8; r++) {
        int idx = r * 128 + i, ii = idx >> 3, h = idx & 7;
        sm[(8 + h) * PAD + ii] = b1[(size_t)(ii * OUTSZ + o) * 8 + h];
    }
#pragma unroll
    for (int r = 0; r < 32; r++) {
        int idx = r * 128 + i, ii = idx >> 5, e = idx & 31;
        sm[(16 + e) * PAD + ii] = W2[(size_t)(ii * OUTSZ + o) * 64 + e];
    }
    __syncthreads();

    u64 w1p[4], b1p[4], w2p[4][8];
#pragma unroll
    for (int p = 0; p < 4; p++) {
        w1p[p] = pk(sm[(2 * p) * PAD + i], sm[(2 * p + 1) * PAD + i]);
        b1p[p] = pk(sm[(8 + 2 * p) * PAD + i], sm[(9 + 2 * p) * PAD + i]);
    }
#pragma unroll
    for (int p = 0; p < 2; p++)
#pragma unroll
        for (int k = 0; k < 8; k++)
            w2p[p][k] = pk(sm[(16 + (2 * p) * 8 + k) * PAD + i],
                           sm[(16 + (2 * p + 1) * 8 + k) * PAD + i]);
    __syncthreads();

    // ===== Phase B staging: W2 e>=32 (r0-31), b2 (r32-39), W3 (r40-47), b3 (r48)
#pragma unroll
    for (int r = 0; r < 32; r++) {
        int idx = r * 128 + i, ii = idx >> 5, e = idx & 31;
        sm[e * PAD + ii] = W2[(size_t)(ii * OUTSZ + o) * 64 + 32 + e];
    }
#pragma unroll
    for (int r = 0; r < 8; r++) {
        int idx = r * 128 + i, ii = idx >> 3, h = idx & 7;
        sm[(32 + h) * PAD + ii] = b2[(size_t)(ii * OUTSZ + o) * 8 + h];
    }
#pragma unroll
    for (int r = 0; r < 8; r++) {
        int idx = r * 128 + i, ii = idx >> 3, h = idx & 7;
        sm[(40 + h) * PAD + ii] = W3[(size_t)(ii * OUTSZ + o) * 8 + h];
    }
    sm[48 * PAD + i] = b3[(size_t)i * OUTSZ + o];
    __syncthreads();

    u64 b2p[4], w3p[4], b3p;
#pragma unroll
    for (int p = 0; p < 2; p++)
#pragma unroll
        for (int k = 0; k < 8; k++)
            w2p[2 + p][k] = pk(sm[((2 * p) * 8 + k) * PAD + i],
                               sm[((2 * p + 1) * 8 + k) * PAD + i]);
#pragma unroll
    for (int p = 0; p < 4; p++) {
        b2p[p] = pk(sm[(32 + 2 * p) * PAD + i], sm[(33 + 2 * p) * PAD + i]);
        w3p[p] = pk(sm[(40 + 2 * p) * PAD + i], sm[(41 + 2 * p) * PAD + i]);
    }
    b3p = pk(sm[48 * PAD + i], 0.0f);   // bias folds into low half of chain 0
    __syncthreads();                    // sm now reusable as red/pr

    // ===================== main loop: 2 x 64-elem supersteps ================
#pragma unroll 1
    for (int s64 = 0; s64 < 2; s64++) {
#pragma unroll 1
        for (int g = 0; g < 8; g++) {
#pragma unroll
            for (int u = 0; u < 8; u++) {
                const int b = s64 * 64 + g * 8 + u;
                float v = vbuf[u];
                vbuf[u] = xp[(size_t)((b + 8) & 127) * INSZ];  // wrap prefetch

                u64 vp = pk(v, v);

                // layer 1: h1 = relu(w1*v + b1) -> splatted pairs s[k]
                u64 s[8];
#pragma unroll
                for (int p = 0; p < 4; p++) {
                    u64 t = ffma2(w1p[p], vp, b1p[p]);
                    float ta, tb; upk(t, ta, tb);
                    ta = fmaxf(ta, 0.0f);
                    tb = fmaxf(tb, 0.0f);
                    s[2 * p]     = pk(ta, ta);
                    s[2 * p + 1] = pk(tb, tb);
                }

                // layer 2: 4 packed output-pairs, 8-deep chains (4-way ILP)
                u64 h[4];
#pragma unroll
                for (int q = 0; q < 4; q++) {
                    u64 acc = ffma2(w2p[q][0], s[0], b2p[q]);
#pragma unroll
                    for (int k = 1; k < 8; k++) acc = ffma2(w2p[q][k], s[k], acc);
                    float ha, hb; upk(acc, ha, hb);
                    h[q] = pk(fmaxf(ha, 0.0f), fmaxf(hb, 0.0f));
                }

                // layer 3: two 2-deep chains + packed combine
                u64 a0 = ffma2(w3p[0], h[0], b3p);
                u64 a1 = fmul2(w3p[1], h[1]);
                a0 = ffma2(w3p[2], h[2], a0);
                a1 = ffma2(w3p[3], h[3], a1);
                u64 t = fadd2(a0, a1);
                float x0, x1; upk(t, x0, x1);

                red[(g * 8 + u) * 129 + i] = x0 + x1;
            }
        }
        __syncthreads();

        // stage-1 reduction: thread t handles tasks (q0 = t>>6, bb = t&63)
        // and (q0+2, bb): each sums 32 i-values of row bb.
        {
            const int bb = i & 63, q0 = i >> 6;
#pragma unroll
            for (int tk = 0; tk < 2; tk++) {
                const int q = q0 + 2 * tk;
                const float* rr = &red[bb * 129 + q * 32];
                float s0 = 0.f, s1 = 0.f, s2 = 0.f, s3 = 0.f;
#pragma unroll
                for (int c = 0; c < 32; c += 4) {
                    s0 += rr[c + 0]; s1 += rr[c + 1];
                    s2 += rr[c + 2]; s3 += rr[c + 3];
                }
                pr[q * 65 + bb] = (s0 + s1) + (s2 + s3);
            }
        }
        __syncthreads();

        // stage-2: 64 threads combine 4 partials + store (overlaps next compute)
        if (i < 64) {
            float r = (pr[i] + pr[65 + i]) + (pr[130 + i] + pr[195 + i]);
            out[(size_t)(chunk * BC + s64 * 64 + i) * OUTSZ + o] = r;
        }
    }
}

// ---------------------------------------------------------------------------
extern "C" void kernel_launch(void* const* d_in, const int* in_sizes, int n_in,
                              void* d_out, int out_size) {
    const float* x  = (const float*)d_in[0];
    const float* W1 = (const float*)d_in[1];
    const float* b1 = (const float*)d_in[2];
    const float* W2 = (const float*)d_in[3];
    const float* b2 = (const float*)d_in[4];
    const float* W3 = (const float*)d_in[5];
    const float* b3 = (const float*)d_in[6];
    float* out = (float*)d_out;

    mlpkan_fused<<<dim3(OUTSZ, NCHUNK), INSZ>>>(x, W1, b1, W2, b2, W3, b3, out);
}

// round 10
// speedup vs baseline: 1.1846x; 1.0310x over previous
#include <cuda_runtime.h>

// Problem constants
#define INSZ   128
#define OUTSZ  128
#define BATCH  1024

#define NCHUNK 8
#define BC     (BATCH / NCHUNK)   // 128 batch elems per block
#define PAD    133                // smem row pitch (conflict-free staging writes)

typedef unsigned long long u64;

__device__ __forceinline__ u64 pk(float a, float b) {
    u64 r; asm("mov.b64 %0, {%1, %2};" : "=l"(r) : "f"(a), "f"(b)); return r;
}
__device__ __forceinline__ void upk(u64 v, float& a, float& b) {
    asm("mov.b64 {%0, %1}, %2;" : "=f"(a), "=f"(b) : "l"(v));
}
__device__ __forceinline__ u64 ffma2(u64 a, u64 b, u64 c) {
    u64 d; asm("fma.rn.f32x2 %0, %1, %2, %3;" : "=l"(d) : "l"(a), "l"(b), "l"(c)); return d;
}
__device__ __forceinline__ u64 fmul2(u64 a, u64 b) {
    u64 d; asm("mul.rn.f32x2 %0, %1, %2;" : "=l"(d) : "l"(a), "l"(b)); return d;
}
__device__ __forceinline__ u64 fadd2(u64 a, u64 b) {
    u64 d; asm("add.rn.f32x2 %0, %1, %2;" : "=l"(d) : "l"(a), "l"(b)); return d;
}

// ---------------------------------------------------------------------------
// Fused kernel: block = (o, batch-chunk of 128); thread = input feature i.
// j-packed f32x2 core. WARP DE-PHASING: warp w walks the 8 g-groups of each
// 64-elem superstep starting at g0 = (2w)&7, so co-resident warps are ~300
// issue-cycles out of phase and the fma/alu pipes overlap across warps
// instead of colliding in lockstep bursts after each barrier.
// ---------------------------------------------------------------------------
__global__ void __launch_bounds__(128, 3)
mlpkan_fused(const float* __restrict__ x,
             const float* __restrict__ W1, const float* __restrict__ b1,
             const float* __restrict__ W2, const float* __restrict__ b2,
             const float* __restrict__ W3, const float* __restrict__ b3,
             float* __restrict__ out) {
    const int o     = blockIdx.x;
    const int chunk = blockIdx.y;
    const int i     = threadIdx.x;
    const int g0    = ((i >> 5) * 2) & 7;   // per-warp phase rotation

    // union: staging (49*PAD = 6517) vs red (64*129) + pr (4*65)
    __shared__ float sm[64 * 129 + 4 * 65];   // 34.1 KB
    float* red = sm;                          // [64][129]
    float* pr  = sm + 64 * 129;               // [4][65]

    // ---- x prefetch: 8-deep rolling buffer, primed at this warp's start ----
    const float* xp = x + (size_t)chunk * BC * INSZ + i;
    float vbuf[8];
#pragma unroll
    for (int u = 0; u < 8; u++) vbuf[u] = xp[(size_t)(g0 * 8 + u) * INSZ];

    // =========== Phase A staging: W1 (f0-7), b1 (f8-15), W2 e<32 (f16-47) ====
#pragma unroll
    for (int r = 0; r < 8; r++) {
        int idx = r * 128 + i, ii = idx >> 3, h = idx & 7;
        sm[h * PAD + ii] = W1[(size_t)(ii * OUTSZ + o) * 8 + h];
    }
#pragma unroll
    for (int r = 0; r < 8; r++) {
        int idx = r * 128 + i, ii = idx >> 3, h = idx & 7;
        sm[(8 + h) * PAD + ii] = b1[(size_t)(ii * OUTSZ + o) * 8 + h];
    }
#pragma unroll
    for (int r = 0; r < 32; r++) {
        int idx = r * 128 + i, ii = idx >> 5, e = idx & 31;
        sm[(16 + e) * PAD + ii] = W2[(size_t)(ii * OUTSZ + o) * 64 + e];
    }
    __syncthreads();

    u64 w1p[4], b1p[4], w2p[4][8];
#pragma unroll
    for (int p = 0; p < 4; p++) {
        w1p[p] = pk(sm[(2 * p) * PAD + i], sm[(2 * p + 1) * PAD + i]);
        b1p[p] = pk(sm[(8 + 2 * p) * PAD + i], sm[(9 + 2 * p) * PAD + i]);
    }
#pragma unroll
    for (int p = 0; p < 2; p++)
#pragma unroll
        for (int k = 0; k < 8; k++)
            w2p[p][k] = pk(sm[(16 + (2 * p) * 8 + k) * PAD + i],
                           sm[(16 + (2 * p + 1) * 8 + k) * PAD + i]);
    __syncthreads();

    // ===== Phase B staging: W2 e>=32 (r0-31), b2 (r32-39), W3 (r40-47), b3 (r48)
#pragma unroll
    for (int r = 0; r < 32; r++) {
        int idx = r * 128 + i, ii = idx >> 5, e = idx & 31;
        sm[e * PAD + ii] = W2[(size_t)(ii * OUTSZ + o) * 64 + 32 + e];
    }
#pragma unroll
    for (int r = 0; r < 8; r++) {
        int idx = r * 128 + i, ii = idx >> 3, h = idx & 7;
        sm[(32 + h) * PAD + ii] = b2[(size_t)(ii * OUTSZ + o) * 8 + h];
    }
#pragma unroll
    for (int r = 0; r < 8; r++) {
        int idx = r * 128 + i, ii = idx >> 3, h = idx & 7;
        sm[(40 + h) * PAD + ii] = W3[(size_t)(ii * OUTSZ + o) * 8 + h];
    }
    sm[48 * PAD + i] = b3[(size_t)i * OUTSZ + o];
    __syncthreads();

    u64 b2p[4], w3p[4], b3p;
#pragma unroll
    for (int p = 0; p < 2; p++)
#pragma unroll
        for (int k = 0; k < 8; k++)
            w2p[2 + p][k] = pk(sm[((2 * p) * 8 + k) * PAD + i],
                               sm[((2 * p + 1) * 8 + k) * PAD + i]);
#pragma unroll
    for (int p = 0; p < 4; p++) {
        b2p[p] = pk(sm[(32 + 2 * p) * PAD + i], sm[(33 + 2 * p) * PAD + i]);
        w3p[p] = pk(sm[(40 + 2 * p) * PAD + i], sm[(41 + 2 * p) * PAD + i]);
    }
    b3p = pk(sm[48 * PAD + i], 0.0f);   // bias folds into low half of chain 0
    __syncthreads();                    // sm now reusable as red/pr

    // ===================== main loop: 2 x 64-elem supersteps ================
#pragma unroll 1
    for (int s64 = 0; s64 < 2; s64++) {
#pragma unroll 1
        for (int t = 0; t < 8; t++) {                 // step within superstep
            const int gg = (g0 + t) & 7;              // this warp's g-group
            // next g-group this warp will touch (for prefetch targeting):
            const int gn = (g0 + t + 1) & 7;
            const int nbase = (t < 7) ? (s64 * 64 + gn * 8)
                                      : (s64 == 0 ? 64 + g0 * 8 : g0 * 8);
#pragma unroll
            for (int u = 0; u < 8; u++) {
                const int bb = gg * 8 + u;            // elem within superstep
                float v = vbuf[u];
                vbuf[u] = xp[(size_t)(nbase + u) * INSZ];   // own-successor

                u64 vp = pk(v, v);

                // layer 1: h1 = relu(w1*v + b1) -> splatted pairs s[k]
                u64 s[8];
#pragma unroll
                for (int p = 0; p < 4; p++) {
                    u64 tt = ffma2(w1p[p], vp, b1p[p]);
                    float ta, tb; upk(tt, ta, tb);
                    ta = fmaxf(ta, 0.0f);
                    tb = fmaxf(tb, 0.0f);
                    s[2 * p]     = pk(ta, ta);
                    s[2 * p + 1] = pk(tb, tb);
                }

                // layer 2: 4 packed output-pairs, 8-deep chains (4-way ILP)
                u64 h[4];
#pragma unroll
                for (int q = 0; q < 4; q++) {
                    u64 acc = ffma2(w2p[q][0], s[0], b2p[q]);
#pragma unroll
                    for (int k = 1; k < 8; k++) acc = ffma2(w2p[q][k], s[k], acc);
                    float ha, hb; upk(acc, ha, hb);
                    h[q] = pk(fmaxf(ha, 0.0f), fmaxf(hb, 0.0f));
                }

                // layer 3: two 2-deep chains + packed combine
                u64 a0 = ffma2(w3p[0], h[0], b3p);
                u64 a1 = fmul2(w3p[1], h[1]);
                a0 = ffma2(w3p[2], h[2], a0);
                a1 = ffma2(w3p[3], h[3], a1);
                u64 tt = fadd2(a0, a1);
                float x0, x1; upk(tt, x0, x1);

                red[bb * 129 + i] = x0 + x1;
            }
        }
        __syncthreads();

        // stage-1 reduction: thread handles (bb = i&63) for q = i>>6 and q+2
        {
            const int bb = i & 63, q0 = i >> 6;
#pragma unroll
            for (int tk = 0; tk < 2; tk++) {
                const int q = q0 + 2 * tk;
                const float* rr = &red[bb * 129 + q * 32];
                float s0 = 0.f, s1 = 0.f, s2 = 0.f, s3 = 0.f;
#pragma unroll
                for (int c = 0; c < 32; c += 4) {
                    s0 += rr[c + 0]; s1 += rr[c + 1];
                    s2 += rr[c + 2]; s3 += rr[c + 3];
                }
                pr[q * 65 + bb] = (s0 + s1) + (s2 + s3);
            }
        }
        __syncthreads();

        // stage-2: 64 threads combine 4 partials + store
        if (i < 64) {
            float r = (pr[i] + pr[65 + i]) + (pr[130 + i] + pr[195 + i]);
            out[(size_t)(chunk * BC + s64 * 64 + i) * OUTSZ + o] = r;
        }
    }
}

// ---------------------------------------------------------------------------
extern "C" void kernel_launch(void* const* d_in, const int* in_sizes, int n_in,
                              void* d_out, int out_size) {
    const float* x  = (const float*)d_in[0];
    const float* W1 = (const float*)d_in[1];
    const float* b1 = (const float*)d_in[2];
    const float* W2 = (const float*)d_in[3];
    const float* b2 = (const float*)d_in[4];
    const float* W3 = (const float*)d_in[5];
    const float* b3 = (const float*)d_in[6];
    float* out = (float*)d_out;

    mlpkan_fused<<<dim3(OUTSZ, NCHUNK), INSZ>>>(x, W1, b1, W2, b2, W3, b3, out);
}